// round 8
// baseline (speedup 1.0000x reference)
#include <cuda_runtime.h>
#include <cuda_fp16.h>

#define HID 128
#define NMAX 100000
#define NPAD 100096          // NMAX rounded up to 128 for gemm epilogue stores
#define EMAX 1600000
#define GMAX 64
#define SCAN_B 512

// ---- scratch (static device globals; no allocation) ----
__device__ uint2  g_h2h[(size_t)NPAD * 32];   // fp16 messages m[s]=h2[s]*dis[s], [N][128]
__device__ float4 g_acc[(size_t)NMAX * 32];   // aggregated output per layer (fp32)
__device__ float  g_dis[NMAX];                // deg^{-1/2}
__device__ float  g_cnt[GMAX];                // per-graph node counts
__device__ int    g_deg[NMAX];                // in-degree (no self loop)
__device__ int    g_cur[NMAX];                // fill cursor
__device__ int    g_rowptr[NMAX + 1];         // CSR row pointers (by dst)
__device__ __align__(16) int g_csr[EMAX];     // src ids grouped by dst (16B aligned)
__device__ int    g_blksum[(NMAX + SCAN_B - 1) / SCAN_B];

__device__ __forceinline__ int clampi(int v, int hi) {
    return v < 0 ? 0 : (v > hi ? hi : v);
}

// ---- packed f32x2 helpers (Blackwell FFMA2) ----
__device__ __forceinline__ unsigned long long pk2(float x) {
    unsigned long long r;
    asm("mov.b64 %0, {%1, %1};" : "=l"(r) : "f"(x));
    return r;
}
__device__ __forceinline__ void fma2(unsigned long long& d,
                                     unsigned long long a, unsigned long long b) {
    asm("fma.rn.f32x2 %0, %1, %2, %0;" : "+l"(d) : "l"(a), "l"(b));
}
__device__ __forceinline__ float2 up2(unsigned long long v) {
    float2 f;
    asm("mov.b64 {%0, %1}, %2;" : "=f"(f.x), "=f"(f.y) : "l"(v));
    return f;
}

// ---------------------------------------------------------------------------
__global__ void k_init(float* __restrict__ out, int N, int out_elems) {
    int i = blockIdx.x * blockDim.x + threadIdx.x;
    if (i < N) { g_deg[i] = 0; g_cur[i] = 0; }
    if (i < GMAX) g_cnt[i] = 0.0f;
    if (i < out_elems) out[i] = 0.0f;
}

__global__ void k_count(const int* __restrict__ dst, int E, int N) {
    int e = blockIdx.x * blockDim.x + threadIdx.x;
    if (e < E) atomicAdd(&g_deg[clampi(dst[e], N - 1)], 1);
}

// --- exclusive scan of g_deg -> g_rowptr ---
__global__ void k_scan1(int N) {
    __shared__ int sm[SCAN_B];
    int t = threadIdx.x;
    int i = blockIdx.x * SCAN_B + t;
    int v = (i < N) ? g_deg[i] : 0;
    sm[t] = v;
    __syncthreads();
    #pragma unroll
    for (int off = 1; off < SCAN_B; off <<= 1) {
        int x = (t >= off) ? sm[t - off] : 0;
        __syncthreads();
        sm[t] += x;
        __syncthreads();
    }
    if (i < N) g_rowptr[i] = sm[t] - v;          // exclusive
    if (t == SCAN_B - 1) g_blksum[blockIdx.x] = sm[t];
}

// parallel exclusive scan of block sums (nb <= SCAN_B)
__global__ void k_scan2(int nb) {
    __shared__ int sm[SCAN_B];
    int t = threadIdx.x;
    int v = (t < nb) ? g_blksum[t] : 0;
    sm[t] = v;
    __syncthreads();
    #pragma unroll
    for (int off = 1; off < SCAN_B; off <<= 1) {
        int x = (t >= off) ? sm[t - off] : 0;
        __syncthreads();
        sm[t] += x;
        __syncthreads();
    }
    if (t < nb) g_blksum[t] = sm[t] - v;
}

// add block offsets + compute dis = rsqrt(deg+1)
__global__ void k_scan3(int N, int E) {
    int i = blockIdx.x * blockDim.x + threadIdx.x;
    if (i < N) {
        g_rowptr[i] += g_blksum[i / SCAN_B];
        g_dis[i] = rsqrtf((float)(g_deg[i] + 1));
    }
    if (i == 0) g_rowptr[N] = E;
}

__global__ void k_fill(const int* __restrict__ src,
                       const int* __restrict__ dst, int E, int N) {
    int e = blockIdx.x * blockDim.x + threadIdx.x;
    if (e >= E) return;
    int d = clampi(dst[e], N - 1);
    int pos = atomicAdd(&g_cur[d], 1);
    int idx = clampi(g_rowptr[d] + pos, EMAX - 1);
    g_csr[idx] = clampi(src[e], N - 1);
}

// ---------------------------------------------------------------------------
// GEMM: m = fp16( dis[row] * (f(in) @ W) )        <- dis[src] folded here
// f(in) = in (layer 0) ; relu(in + bias_prev) (layers > 0, in = g_acc)
// 256 threads, 128x128 tile. FFMA2 (f32x2) inner loop, columns paired.
// ---------------------------------------------------------------------------
__global__ void __launch_bounds__(256) k_gemm(
    const float* __restrict__ xin,
    const float* __restrict__ W,
    const float* __restrict__ bias,
    int use_acc,
    int N)
{
    extern __shared__ float sm[];
    float* xs = sm;                 // [128][128] transposed + swizzled
    float* ws = sm + 128 * HID;     // [128][128] W, k-major rows (reused as staging)

    const int tid  = threadIdx.x;
    const int base = blockIdx.x * 128;
    const int tx   = tid & 15;
    const int ty   = tid >> 4;

    // --- load W straight: ws[k][n] ---
    {
        const float4* Wv = (const float4*)W;
        #pragma unroll
        for (int i = 0; i < 16; i++) {
            int o = i * 256 + tid;          // 4096 float4
            int k = o >> 5, q = o & 31;
            *(float4*)(ws + k * HID + q * 4) = Wv[o];
        }
    }
    // --- load x tile transposed + swizzled ---
    {
        #pragma unroll
        for (int i = 0; i < 16; i++) {
            int o = i * 256 + tid;
            int r = o >> 5;                 // row (m)
            int q = o & 31;                 // float4 index: k = 4q..4q+3
            float4 v = make_float4(0.f, 0.f, 0.f, 0.f);
            if (base + r < N) {
                if (use_acc) {
                    v = g_acc[(size_t)(base + r) * 32 + q];
                    int k4 = q * 4;
                    v.x = fmaxf(v.x + bias[k4 + 0], 0.0f);
                    v.y = fmaxf(v.y + bias[k4 + 1], 0.0f);
                    v.z = fmaxf(v.z + bias[k4 + 2], 0.0f);
                    v.w = fmaxf(v.w + bias[k4 + 3], 0.0f);
                } else {
                    v = ((const float4*)(xin + (size_t)(base + r) * HID))[q];
                }
            }
            int sw = q & 7;
            int mcol = (((r >> 2) ^ sw) << 2) + (r & 3);
            float vv[4] = {v.x, v.y, v.z, v.w};
            #pragma unroll
            for (int j = 0; j < 4; j++)
                xs[(4 * q + j) * HID + mcol] = vv[j];
        }
    }
    __syncthreads();

    unsigned long long acc[8][4];
    #pragma unroll
    for (int i = 0; i < 8; i++)
        #pragma unroll
        for (int j = 0; j < 4; j++) acc[i][j] = 0ull;

    #pragma unroll 4
    for (int k = 0; k < HID; k++) {
        int sw = (k >> 2) & 7;
        float4 a0 = *(const float4*)(xs + k * HID + ((tx ^ sw) << 2));
        float4 a1 = *(const float4*)(xs + k * HID + (((16 + tx) ^ sw) << 2));
        ulonglong2 b0 = *(const ulonglong2*)(ws + k * HID + ty * 4);
        ulonglong2 b1 = *(const ulonglong2*)(ws + k * HID + 64 + ty * 4);
        float av[8] = {a0.x, a0.y, a0.z, a0.w, a1.x, a1.y, a1.z, a1.w};
        #pragma unroll
        for (int i = 0; i < 8; i++) {
            unsigned long long ap = pk2(av[i]);
            fma2(acc[i][0], ap, b0.x);
            fma2(acc[i][1], ap, b0.y);
            fma2(acc[i][2], ap, b1.x);
            fma2(acc[i][3], ap, b1.y);
        }
    }

    // --- epilogue: stage fp32 into ws, then scale by dis[row] + fp16 stores ---
    __syncthreads();           // everyone done reading ws
    #pragma unroll
    for (int i = 0; i < 8; i++) {
        int m = (i < 4) ? (4 * tx + i) : (64 + 4 * tx + (i - 4));
        float* row = ws + m * HID + ty * 4;
        *(float2*)(row)          = up2(acc[i][0]);
        *(float2*)(row + 2)      = up2(acc[i][1]);
        *(float2*)(row + 64)     = up2(acc[i][2]);
        *(float2*)(row + 64 + 2) = up2(acc[i][3]);
    }
    __syncthreads();

    // thread tid handles half a row: row = tid>>1 (64 floats)
    {
        int rloc = tid >> 1;
        float ds = g_dis[clampi(base + rloc, NMAX - 1)];
        const float4* srcv = (const float4*)ws + tid * 16;
        uint4* dst = (uint4*)g_h2h;
        size_t h4 = ((size_t)base * HID + (size_t)tid * 64) >> 3;  // uint4 index
        #pragma unroll
        for (int i = 0; i < 8; i++) {
            float4 p = srcv[i * 2];
            float4 q = srcv[i * 2 + 1];
            __half2 h0 = __floats2half2_rn(p.x * ds, p.y * ds);
            __half2 h1 = __floats2half2_rn(p.z * ds, p.w * ds);
            __half2 h2 = __floats2half2_rn(q.x * ds, q.y * ds);
            __half2 h3 = __floats2half2_rn(q.z * ds, q.w * ds);
            uint4 u;
            u.x = *(unsigned*)&h0; u.y = *(unsigned*)&h1;
            u.z = *(unsigned*)&h2; u.w = *(unsigned*)&h3;
            dst[h4 + i] = u;
        }
    }
}

// ---------------------------------------------------------------------------
// gather-aggregate: one warp per dst node. Messages already carry dis[src]:
// acc[n] = dn * ( sum_{s in in(n)} m[s] + m[n] )
//   (self term: dn*m[n] = dn^2*h2[n]; edge terms: dn*m[s] = dn*ds*h2[s])
// Edge loop: pure row-sum, unrolled x4 via int4 loads of contiguous csr.
// ---------------------------------------------------------------------------
__device__ __forceinline__ void add_row(float4& a, int s, int lane) {
    uint2 v = g_h2h[(size_t)s * 32 + lane];
    float2 g0 = __half22float2(*(__half2*)&v.x);
    float2 g1 = __half22float2(*(__half2*)&v.y);
    a.x += g0.x; a.y += g0.y; a.z += g1.x; a.w += g1.y;
}

__global__ void __launch_bounds__(256) k_aggr(int N) {
    int w    = (int)((blockIdx.x * (unsigned)blockDim.x + threadIdx.x) >> 5);
    int lane = threadIdx.x & 31;
    if (w >= N) return;

    int beg = clampi(g_rowptr[w],     EMAX);
    int end = clampi(g_rowptr[w + 1], EMAX);
    float dn = g_dis[w];

    // self term: m[n] (outer dn multiply supplies the second dis factor)
    uint2 u = g_h2h[(size_t)w * 32 + lane];
    float2 f0 = __half22float2(*(__half2*)&u.x);
    float2 f1 = __half22float2(*(__half2*)&u.y);
    float4 a0 = make_float4(f0.x, f0.y, f1.x, f1.y);
    float4 a1 = make_float4(0.f, 0.f, 0.f, 0.f);

    int e = beg;
    // peel to 16B alignment of g_csr
    for (; e < end && (e & 3); e++) add_row(a0, g_csr[e], lane);
    // main: 4 edges per iteration, two accumulators (MLP)
    for (; e + 4 <= end; e += 4) {
        int4 s4 = *(const int4*)(g_csr + e);
        add_row(a0, s4.x, lane);
        add_row(a1, s4.y, lane);
        add_row(a0, s4.z, lane);
        add_row(a1, s4.w, lane);
    }
    for (; e < end; e++) add_row(a1, g_csr[e], lane);

    g_acc[(size_t)w * 32 + lane] = make_float4(
        dn * (a0.x + a1.x), dn * (a0.y + a1.y),
        dn * (a0.z + a1.z), dn * (a0.w + a1.w));
}

// ---------------------------------------------------------------------------
// pooling (batch sorted): running sums, flush on graph-id change
// ---------------------------------------------------------------------------
#define POOL_CHUNK 256
__global__ void __launch_bounds__(HID) k_pool(
    const int* __restrict__ batch,
    const float* __restrict__ bias,
    float* __restrict__ out,
    int N)
{
    int j     = threadIdx.x;
    int start = blockIdx.x * POOL_CHUNK;
    if (start >= N) return;
    int end = start + POOL_CHUNK;
    if (end > N) end = N;

    const float* accf = (const float*)g_acc;

    float b   = bias[j];
    int   cur = clampi(batch[start], GMAX - 1);
    float sum = 0.0f;
    float cnt = 0.0f;

    for (int r = start; r < end; r++) {
        int g = clampi(batch[r], GMAX - 1);
        if (g != cur) {
            atomicAdd(out + (size_t)cur * HID + j, sum);
            if (j == 0) atomicAdd(&g_cnt[cur], cnt);
            sum = 0.0f; cnt = 0.0f; cur = g;
        }
        sum += fmaxf(accf[(size_t)r * HID + j] + b, 0.0f);
        cnt += 1.0f;
    }
    atomicAdd(out + (size_t)cur * HID + j, sum);
    if (j == 0) atomicAdd(&g_cnt[cur], cnt);
}

__global__ void k_div(float* __restrict__ out, int out_elems) {
    int i = blockIdx.x * blockDim.x + threadIdx.x;
    if (i < out_elems) out[i] /= fmaxf(g_cnt[i >> 7], 1.0f);
}

// ---------------------------------------------------------------------------
extern "C" void kernel_launch(void* const* d_in, const int* in_sizes, int n_in,
                              void* d_out, int out_size) {
    const float* x     = (const float*)d_in[0];
    const int*   ei    = (const int*)d_in[1];     // int32 (JAX x64 disabled)
    const int*   batch = (const int*)d_in[2];     // int32
    const float* Ws    = (const float*)d_in[3];
    const float* bs    = (const float*)d_in[4];
    float*       out   = (float*)d_out;

    const int N = in_sizes[0] / HID;
    const int E = in_sizes[1] / 2;
    const int* srcp = ei;
    const int* dstp = ei + E;

    const size_t smem = 2 * 128 * HID * sizeof(float);   // 128 KB
    cudaFuncSetAttribute(k_gemm, cudaFuncAttributeMaxDynamicSharedMemorySize,
                         (int)smem);

    const int nb_scan = (N + SCAN_B - 1) / SCAN_B;

    k_init  <<<(N + 255) / 256, 256>>>(out, N, out_size);
    k_count <<<(E + 255) / 256, 256>>>(dstp, E, N);
    k_scan1 <<<nb_scan, SCAN_B>>>(N);
    k_scan2 <<<1, SCAN_B>>>(nb_scan);
    k_scan3 <<<(N + 255) / 256, 256>>>(N, E);
    k_fill  <<<(E + 255) / 256, 256>>>(srcp, dstp, E, N);

    const int gemm_blocks = (N + 127) / 128;
    const int aggr_blocks = (int)(((long long)N * 32 + 255) / 256);

    for (int l = 0; l < 3; l++) {
        const float* bias_prev = (l == 0) ? bs : (bs + (size_t)(l - 1) * HID);
        k_gemm<<<gemm_blocks, 256, smem>>>(
            x, Ws + (size_t)l * HID * HID, bias_prev, l > 0 ? 1 : 0, N);
        k_aggr<<<aggr_blocks, 256>>>(N);
    }

    k_pool<<<(N + POOL_CHUNK - 1) / POOL_CHUNK, HID>>>(batch, bs + 2 * HID, out, N);
    k_div <<<(out_size + 255) / 256, 256>>>(out, out_size);
}

// round 12
// speedup vs baseline: 1.9733x; 1.9733x over previous
#include <cuda_runtime.h>
#include <cuda_fp16.h>
#include <mma.h>

using namespace nvcuda;

#define HID 128
#define NMAX 100000
#define NPAD 100096
#define EMAX 1600000
#define GMAX 64
#define SCAN_B 512
#define LDAB 136            // fp16 row stride in smem (padded)
#define LDC  132            // fp32 staging row stride

// ---- scratch (static device globals; no allocation) ----
__device__ uint2 g_m[(size_t)NPAD * 32];   // fp16 messages m=h2*dis, [node][128]
__device__ uint2 g_y[(size_t)NPAD * 32];   // fp16 activations relu(agg+bias)
__device__ float g_dis[NMAX];              // deg^{-1/2}
__device__ float g_cnt[GMAX];
__device__ int   g_deg[NMAX];
__device__ int   g_cur[NMAX];
__device__ int   g_rowptr[NMAX + 1];
__device__ __align__(16) int g_csr[EMAX];
__device__ int   g_blksum[(NMAX + SCAN_B - 1) / SCAN_B];

__device__ __forceinline__ int clampi(int v, int hi) {
    return v < 0 ? 0 : (v > hi ? hi : v);
}

// ---- fp16 pack/unpack ----
__device__ __forceinline__ unsigned pack_hf2(float lo, float hi) {
    __half2 h = __floats2half2_rn(lo, hi);
    return *(unsigned*)&h;
}
__device__ __forceinline__ float4 unpk_hf4(uint2 v) {
    float2 f0 = __half22float2(*(__half2*)&v.x);
    float2 f1 = __half22float2(*(__half2*)&v.y);
    return make_float4(f0.x, f0.y, f1.x, f1.y);
}

// ---------------------------------------------------------------------------
__global__ void k_init(float* __restrict__ out, int N, int out_elems) {
    int i = blockIdx.x * blockDim.x + threadIdx.x;
    if (i < N) { g_deg[i] = 0; g_cur[i] = 0; }
    if (i < GMAX) g_cnt[i] = 0.0f;
    if (i < out_elems) out[i] = 0.0f;
}

__global__ void k_count(const int* __restrict__ dst, int E, int N) {
    int e = blockIdx.x * blockDim.x + threadIdx.x;
    if (e < E) atomicAdd(&g_deg[clampi(dst[e], N - 1)], 1);
}

// scan stage 1 + dis = rsqrt(deg+1)
__global__ void k_scan1(int N) {
    __shared__ int sm[SCAN_B];
    int t = threadIdx.x;
    int i = blockIdx.x * SCAN_B + t;
    int v = (i < N) ? g_deg[i] : 0;
    sm[t] = v;
    __syncthreads();
    #pragma unroll
    for (int off = 1; off < SCAN_B; off <<= 1) {
        int x = (t >= off) ? sm[t - off] : 0;
        __syncthreads();
        sm[t] += x;
        __syncthreads();
    }
    if (i < N) {
        g_rowptr[i] = sm[t] - v;
        g_dis[i] = rsqrtf((float)(v + 1));
    }
    if (t == SCAN_B - 1) g_blksum[blockIdx.x] = sm[t];
}

__global__ void k_scan2(int nb) {
    __shared__ int sm[SCAN_B];
    int t = threadIdx.x;
    int v = (t < nb) ? g_blksum[t] : 0;
    sm[t] = v;
    __syncthreads();
    #pragma unroll
    for (int off = 1; off < SCAN_B; off <<= 1) {
        int x = (t >= off) ? sm[t - off] : 0;
        __syncthreads();
        sm[t] += x;
        __syncthreads();
    }
    if (t < nb) g_blksum[t] = sm[t] - v;
}

__global__ void k_scan3(int N, int E) {
    int i = blockIdx.x * blockDim.x + threadIdx.x;
    if (i < N) g_rowptr[i] += g_blksum[i / SCAN_B];
    if (i == 0) g_rowptr[N] = E;
}

__global__ void k_fill(const int* __restrict__ src,
                       const int* __restrict__ dst, int E, int N) {
    int e = blockIdx.x * blockDim.x + threadIdx.x;
    if (e >= E) return;
    int d = clampi(dst[e], N - 1);
    int pos = atomicAdd(&g_cur[d], 1);
    int idx = clampi(g_rowptr[d] + pos, EMAX - 1);
    g_csr[idx] = clampi(src[e], N - 1);
}

// ---------------------------------------------------------------------------
// WMMA GEMM tile (fp16 in, fp32 accum): m[r] = fp16( dis[r] * (A[r] @ W) )
// A = x (layer 0) or g_y. 256 threads = 8 warps, warp w: rows 16w..16w+15.
// ---------------------------------------------------------------------------
__global__ void __launch_bounds__(256) k_gemm_wmma(
    const float* __restrict__ xin,
    const float* __restrict__ W,
    int layer, int N)
{
    extern __shared__ char smch[];
    __half* As = (__half*)smch;               // [128][LDAB]
    __half* Bs = As + 128 * LDAB;             // [128][LDAB]
    float*  Cs = (float*)smch;                // [128][LDC] (reuse)

    const int tid  = threadIdx.x;
    const int w    = tid >> 5;
    const int base = blockIdx.x * 128;

    // --- W -> Bs (fp16), k-major rows ---
    {
        const float4* Wv = (const float4*)W;
        #pragma unroll
        for (int i = 0; i < 16; i++) {
            int o = i * 256 + tid;          // 4096 float4
            int k = o >> 5, q = o & 31;
            float4 v = Wv[o];
            *(uint2*)(Bs + k * LDAB + q * 4) =
                make_uint2(pack_hf2(v.x, v.y), pack_hf2(v.z, v.w));
        }
    }
    // --- A -> As (fp16) ---
    {
        #pragma unroll
        for (int i = 0; i < 16; i++) {
            int o = i * 256 + tid;
            int r = o >> 5, q = o & 31;
            uint2 u = make_uint2(0u, 0u);
            if (base + r < N) {
                if (layer == 0) {
                    float4 v = ((const float4*)(xin + (size_t)(base + r) * HID))[q];
                    u = make_uint2(pack_hf2(v.x, v.y), pack_hf2(v.z, v.w));
                } else {
                    u = g_y[(size_t)(base + r) * 32 + q];
                }
            }
            *(uint2*)(As + r * LDAB + q * 4) = u;
        }
    }
    __syncthreads();

    // --- compute: 8 accumulators of 16x16 per warp ---
    wmma::fragment<wmma::accumulator, 16, 16, 16, float> acc[8];
    #pragma unroll
    for (int j = 0; j < 8; j++) wmma::fill_fragment(acc[j], 0.0f);

    #pragma unroll
    for (int ks = 0; ks < 8; ks++) {
        wmma::fragment<wmma::matrix_a, 16, 16, 16, __half, wmma::row_major> af;
        wmma::load_matrix_sync(af, As + (w * 16) * LDAB + ks * 16, LDAB);
        #pragma unroll
        for (int j = 0; j < 8; j++) {
            wmma::fragment<wmma::matrix_b, 16, 16, 16, __half, wmma::row_major> bf;
            wmma::load_matrix_sync(bf, Bs + (ks * 16) * LDAB + j * 16, LDAB);
            wmma::mma_sync(acc[j], af, bf, acc[j]);
        }
    }
    __syncthreads();            // done reading As/Bs; reuse as staging

    #pragma unroll
    for (int j = 0; j < 8; j++)
        wmma::store_matrix_sync(Cs + (w * 16) * LDC + j * 16, acc[j], LDC,
                                wmma::mem_row_major);
    __syncthreads();

    // --- epilogue: scale by dis[row], pack fp16, store g_m coalesced ---
    {
        int r    = tid >> 1;            // row in tile
        int half = tid & 1;             // 64-col half
        int m    = base + r;
        if (m < N) {
            float ds = g_dis[m];
            const float* row = Cs + r * LDC + half * 64;
            // 16 uint4 per node (256 B); this thread's half = 8 uint4
            uint4* dst = (uint4*)g_m + (size_t)m * 16 + half * 8;
            #pragma unroll
            for (int i = 0; i < 4; i++) {
                float4 p = *(const float4*)(row + i * 16 + 0);
                float4 q = *(const float4*)(row + i * 16 + 4);
                float4 s = *(const float4*)(row + i * 16 + 8);
                float4 t = *(const float4*)(row + i * 16 + 12);
                uint4 u0;
                u0.x = pack_hf2(p.x * ds, p.y * ds);
                u0.y = pack_hf2(p.z * ds, p.w * ds);
                u0.z = pack_hf2(q.x * ds, q.y * ds);
                u0.w = pack_hf2(q.z * ds, q.w * ds);
                uint4 u1;
                u1.x = pack_hf2(s.x * ds, s.y * ds);
                u1.y = pack_hf2(s.z * ds, s.w * ds);
                u1.z = pack_hf2(t.x * ds, t.y * ds);
                u1.w = pack_hf2(t.z * ds, t.w * ds);
                dst[i * 2 + 0] = u0;
                dst[i * 2 + 1] = u1;
            }
        }
    }
}

// ---------------------------------------------------------------------------
// aggregate: warp per node. y[n] = relu( dn*(sum_in m[s] + m[n]) + bias )
// ---------------------------------------------------------------------------
__device__ __forceinline__ void add_row(float4& a, int s, int lane) {
    float4 g = unpk_hf4(g_m[(size_t)s * 32 + lane]);
    a.x += g.x; a.y += g.y; a.z += g.z; a.w += g.w;
}

__global__ void __launch_bounds__(256) k_aggr(const float* __restrict__ bias, int N) {
    int w    = (int)((blockIdx.x * (unsigned)blockDim.x + threadIdx.x) >> 5);
    int lane = threadIdx.x & 31;
    if (w >= N) return;

    int beg = clampi(g_rowptr[w],     EMAX);
    int end = clampi(g_rowptr[w + 1], EMAX);
    float dn = g_dis[w];

    float4 a0 = unpk_hf4(g_m[(size_t)w * 32 + lane]);   // self term m[n]
    float4 a1 = make_float4(0.f, 0.f, 0.f, 0.f);

    int e = beg;
    for (; e < end && (e & 3); e++) add_row(a0, g_csr[e], lane);
    for (; e + 4 <= end; e += 4) {
        int4 s4 = *(const int4*)(g_csr + e);
        add_row(a0, s4.x, lane);
        add_row(a1, s4.y, lane);
        add_row(a0, s4.z, lane);
        add_row(a1, s4.w, lane);
    }
    for (; e < end; e++) add_row(a1, g_csr[e], lane);

    float4 b = ((const float4*)bias)[lane];
    float y0 = fmaxf(dn * (a0.x + a1.x) + b.x, 0.0f);
    float y1 = fmaxf(dn * (a0.y + a1.y) + b.y, 0.0f);
    float y2 = fmaxf(dn * (a0.z + a1.z) + b.z, 0.0f);
    float y3 = fmaxf(dn * (a0.w + a1.w) + b.w, 0.0f);
    g_y[(size_t)w * 32 + lane] = make_uint2(pack_hf2(y0, y1), pack_hf2(y2, y3));
}

// ---------------------------------------------------------------------------
// pooling (batch sorted): y already has bias+relu
// ---------------------------------------------------------------------------
#define POOL_CHUNK 256
__global__ void __launch_bounds__(HID) k_pool(
    const int* __restrict__ batch,
    float* __restrict__ out,
    int N)
{
    int j     = threadIdx.x;
    int start = blockIdx.x * POOL_CHUNK;
    if (start >= N) return;
    int end = start + POOL_CHUNK;
    if (end > N) end = N;

    const __half* yh = (const __half*)g_y;

    int   cur = clampi(batch[start], GMAX - 1);
    float sum = 0.0f;
    float cnt = 0.0f;

    for (int r = start; r < end; r++) {
        int g = clampi(batch[r], GMAX - 1);
        if (g != cur) {
            atomicAdd(out + (size_t)cur * HID + j, sum);
            if (j == 0) atomicAdd(&g_cnt[cur], cnt);
            sum = 0.0f; cnt = 0.0f; cur = g;
        }
        sum += __half2float(yh[(size_t)r * HID + j]);
        cnt += 1.0f;
    }
    atomicAdd(out + (size_t)cur * HID + j, sum);
    if (j == 0) atomicAdd(&g_cnt[cur], cnt);
}

__global__ void k_div(float* __restrict__ out, int out_elems) {
    int i = blockIdx.x * blockDim.x + threadIdx.x;
    if (i < out_elems) out[i] /= fmaxf(g_cnt[i >> 7], 1.0f);
}

// ---------------------------------------------------------------------------
extern "C" void kernel_launch(void* const* d_in, const int* in_sizes, int n_in,
                              void* d_out, int out_size) {
    const float* x     = (const float*)d_in[0];
    const int*   ei    = (const int*)d_in[1];     // int32 (JAX x64 disabled)
    const int*   batch = (const int*)d_in[2];     // int32
    const float* Ws    = (const float*)d_in[3];
    const float* bs    = (const float*)d_in[4];
    float*       out   = (float*)d_out;

    const int N = in_sizes[0] / HID;
    const int E = in_sizes[1] / 2;
    const int* srcp = ei;
    const int* dstp = ei + E;

    const int smem = 2 * 128 * LDAB * sizeof(__half);   // 69632 B
    cudaFuncSetAttribute(k_gemm_wmma,
                         cudaFuncAttributeMaxDynamicSharedMemorySize, smem);

    const int nb_scan     = (N + SCAN_B - 1) / SCAN_B;
    const int gemm_blocks = (N + 127) / 128;
    const int aggr_blocks = (int)(((long long)N * 32 + 255) / 256);

    // launch order puts layer-0 GEMM at index 3 so ncu captures it
    k_init  <<<(N + 255) / 256, 256>>>(out, N, out_size);               // 0
    k_count <<<(E + 255) / 256, 256>>>(dstp, E, N);                     // 1
    k_scan1 <<<nb_scan, SCAN_B>>>(N);                                   // 2
    k_gemm_wmma<<<gemm_blocks, 256, smem>>>(x, Ws, 0, N);               // 3 <- profiled
    k_scan2 <<<1, SCAN_B>>>(nb_scan);                                   // 4
    k_scan3 <<<(N + 255) / 256, 256>>>(N, E);                           // 5
    k_fill  <<<(E + 255) / 256, 256>>>(srcp, dstp, E, N);               // 6

    k_aggr  <<<aggr_blocks, 256>>>(bs, N);                              // layer 0
    for (int l = 1; l < 3; l++) {
        k_gemm_wmma<<<gemm_blocks, 256, smem>>>(x, Ws + (size_t)l * HID * HID, l, N);
        k_aggr  <<<aggr_blocks, 256>>>(bs + (size_t)l * HID, N);
    }

    k_pool<<<(N + POOL_CHUNK - 1) / POOL_CHUNK, HID>>>(batch, out, N);
    k_div <<<(out_size + 255) / 256, 256>>>(out, out_size);
}